// round 15
// baseline (speedup 1.0000x reference)
#include <cuda_runtime.h>
#include <cstdint>

#define IN_CH   64
#define OUT_CH  128
#define HW      128
#define IMG     (HW*HW)         // 16384
#define NB      16
#define KS      576             // IN_CH * 9
#define KW4     (KS/4)          // 144 words per row
#define M_TOTAL (NB*IMG)        // 262144
#define NTILES  (M_TOTAL/64)    // 4096
#define GRID_P  296             // persistent: 2 CTAs x 148 SMs

// ---------------- device scratch (static, no allocation) ----------------
__device__ unsigned int g_act9[KS];
__device__ float        g_scale[KS];
__device__ float        g_recip[KS];
__device__ float        g_params[4];                  // [0]=s_x, [1]=s_x*s_w, [2]=s_w
__device__ unsigned int g_qw[OUT_CH*KW4];             // int8 weights [o][k] packed

// ---------------- k0: zero the atomicMax target ----------------
__global__ void k_zero() {
    int t = threadIdx.x;
    if (t < KS) g_act9[t] = 0u;
}

// ---------------- k1: per-(c,kh,kw) activation amax over valid window ----------------
__global__ void k_act9(const float* __restrict__ in) {
    const float* p = in + (size_t)blockIdx.x * IMG;   // blockIdx = b*64 + c
    float loc[9];
#pragma unroll
    for (int i = 0; i < 9; i++) loc[i] = 0.f;

    for (int idx = threadIdx.x; idx < IMG; idx += blockDim.x) {
        int r = idx >> 7, c = idx & 127;
        float a = fabsf(p[idx]);
        bool rok[3] = { r <= 126, true, r >= 1 };
        bool cok[3] = { c <= 126, true, c >= 1 };
#pragma unroll
        for (int kh = 0; kh < 3; kh++)
#pragma unroll
            for (int kw = 0; kw < 3; kw++) {
                float v = (rok[kh] && cok[kw]) ? a : 0.f;
                loc[kh*3+kw] = fmaxf(loc[kh*3+kw], v);
            }
    }
#pragma unroll
    for (int i = 0; i < 9; i++)
        for (int o = 16; o > 0; o >>= 1)
            loc[i] = fmaxf(loc[i], __shfl_xor_sync(0xffffffffu, loc[i], o));

    __shared__ float sred[8][9];
    int wid = threadIdx.x >> 5, lane = threadIdx.x & 31;
    if (lane == 0)
        for (int i = 0; i < 9; i++) sred[wid][i] = loc[i];
    __syncthreads();
    if (threadIdx.x < 9) {
        float m = sred[0][threadIdx.x];
        for (int w = 1; w < 8; w++) m = fmaxf(m, sred[w][threadIdx.x]);
        int c = blockIdx.x & 63;
        atomicMax(&g_act9[c*9 + threadIdx.x], __float_as_uint(m));
    }
}

// ---------------- k2: scales + amaxes (weight quant moved to k_quantw) ----------------
__global__ void k_scales(const float* __restrict__ w) {
    __shared__ float red[KS];
    int t = threadIdx.x;

    float wm = 0.f;
    for (int o = 0; o < OUT_CH; o++) wm = fmaxf(wm, fabsf(w[o*KS + t]));

    float a = __uint_as_float(g_act9[t]);
    float s = __fdiv_rn(sqrtf(a), sqrtf(wm));
    if (s == 0.f) s = 1.f;
    g_scale[t] = s;

    red[t] = __fdiv_rn(a, s);
    __syncthreads();
    for (int st = 512; st > 0; st >>= 1) {
        if (t < st && t + st < KS) red[t] = fmaxf(red[t], red[t+st]);
        __syncthreads();
    }
    float xa = red[0];
    __syncthreads();

    float wq = 0.f;
    for (int o = 0; o < OUT_CH; o++) wq = fmaxf(wq, fabsf(w[o*KS + t] * s));
    red[t] = wq;
    __syncthreads();
    for (int st = 512; st > 0; st >>= 1) {
        if (t < st && t + st < KS) red[t] = fmaxf(red[t], red[t+st]);
        __syncthreads();
    }
    float wa = red[0];

    float sx = (xa > 0.f) ? __fdiv_rn(xa, 127.f) : 1.f;
    float sw = (wa > 0.f) ? __fdiv_rn(wa, 127.f) : 1.f;

    g_recip[t] = (float)(1.0 / ((double)s * (double)sx));
    if (t == 0) { g_params[0] = sx; g_params[1] = sx * sw; g_params[2] = sw; }
}

// ---------------- k2b: weight quantization, one block per output channel ----------------
__global__ void k_quantw(const float* __restrict__ w) {
    int o = blockIdx.x, t = threadIdx.x;               // 576 threads
    float sw = g_params[2];
    float v = w[o*KS + t] * g_scale[t];
    float q = rintf(__fdiv_rn(v, sw));                 // exact reference chain
    q = fminf(fmaxf(q, -127.f), 127.f);
    ((unsigned char*)g_qw)[o*KS + t] = (unsigned char)(signed char)(int)q;
}

// ---------------- k3: FUSED quantize + int8 GEMM, persistent, 2 CTAs/SM ----------------
// BM=64, BN=128, K=576 resident. Grid=296 persistent CTAs, each loops tiles
// t = bid + 296*i. B staged once per CTA. Per tile: zero A -> build A (MLP=4
// batched LDG.128 + quantize scatter) -> mainloop (mma.sync m16n8k32) ->
// single-pass epilogue staged in the A region. 5 syncs/tile.
#define BM 64
#define ASTRIDE 592
#define SMEM_B_OFF (BM*ASTRIDE)                       // 37888
#define SMEM_GEMM_TOTAL (SMEM_B_OFF + 128*ASTRIDE)    // 113664

__device__ __forceinline__ void mma_i8(int* c, const int* a, const int* b) {
    asm volatile(
        "mma.sync.aligned.m16n8k32.row.col.s32.s8.s8.s32 "
        "{%0,%1,%2,%3}, {%4,%5,%6,%7}, {%8,%9}, {%0,%1,%2,%3};"
        : "+r"(c[0]), "+r"(c[1]), "+r"(c[2]), "+r"(c[3])
        : "r"(a[0]), "r"(a[1]), "r"(a[2]), "r"(a[3]), "r"(b[0]), "r"(b[1]));
}

extern __shared__ unsigned char smg[];

__global__ void __launch_bounds__(256, 2) k_gemm(const float* __restrict__ in,
                                                 float* __restrict__ out) {
    int tid = threadIdx.x;
    int wid = tid >> 5, lane = tid & 31;
    int wm = wid >> 2, wn = wid & 3;       // warp tile: rows wm*32.., cols wn*32..
    int g  = lane >> 2, tg = lane & 3;     // groupID / threadInGroup

    // ---- stage B once (weights, 128 rows x 576B): LDG.128 -> STS.128 ----
    const uint4* gB = (const uint4*)g_qw;
    for (int idx = tid; idx < 128*36; idx += 256) {
        int row = idx / 36, j = idx - row*36;
        *(uint4*)(smg + SMEM_B_OFF + row*ASTRIDE + j*16) = gB[(size_t)row*36 + j];
    }

    float sxsw = g_params[1];
    const unsigned char* aB = smg + (wm*32 + g)*ASTRIDE + tg*4;
    const unsigned char* bB = smg + SMEM_B_OFF + (wn*32 + g)*ASTRIDE + tg*4;
    float* sC = (float*)smg;               // epilogue staging: [128][68] f32 in A region

    for (int t = blockIdx.x; t < NTILES; t += GRID_P) {
        int m0 = t * BM;
        int b  = m0 >> 14;                 // batch
        int h  = (m0 >> 7) & 127;          // image row
        int w0 = m0 & 127;                 // 0 or 64
        int l0 = m0 & 16383;

        // ---- zero-init A region (covers all padding cases) ----
        for (int idx = tid; idx < BM*37; idx += 256)
            *(uint4*)(smg + idx*16) = make_uint4(0,0,0,0);
        __syncthreads();                   // SYNC1: zero done before scatter

        // ---- build A: batched (MLP=4) float4 loads, quantize, scatter bytes ----
        // planes: (c 0..63, r 0..2), 18 aligned float4 chunks each over cols [w0-4, w0+68)
        for (int base = tid; base < 3456; base += 1024) {
            float4 xv[4];
            int kb[4], wb[4];
            bool ok[4];
#pragma unroll
            for (int u = 0; u < 4; u++) {
                int idx = base + u*256;
                ok[u] = false;
                if (idx < 3456) {
                    int plane = idx / 18;
                    int i     = idx - plane*18;
                    int c     = plane / 3;
                    int r     = plane - 3*c;
                    int ih    = h + r - 1;
                    int col0  = w0 - 4 + i*4;
                    if ((unsigned)ih < (unsigned)HW && col0 >= 0 && col0 < HW) {
                        ok[u] = true;
                        xv[u] = *(const float4*)(in + ((size_t)(b*IN_CH + c)*HW + ih)*HW + col0);
                        kb[u] = c*9 + r*3;
                        wb[u] = col0 - w0 + 1;        // wl for e=0, kw=0
                    }
                }
            }
#pragma unroll
            for (int u = 0; u < 4; u++) {
                if (!ok[u]) continue;
                float R0 = g_recip[kb[u] + 0];
                float R1 = g_recip[kb[u] + 1];
                float R2 = g_recip[kb[u] + 2];
                float Rk[3] = {R0, R1, R2};
                float v4[4] = {xv[u].x, xv[u].y, xv[u].z, xv[u].w};
#pragma unroll
                for (int e = 0; e < 4; e++) {
#pragma unroll
                    for (int kw = 0; kw < 3; kw++) {
                        int wl = wb[u] + e - kw;
                        if ((unsigned)wl < (unsigned)BM) {
                            float tq = v4[e] * Rk[kw];
                            tq = fminf(fmaxf(tq, -127.f), 127.f);
                            int q = __float2int_rn(tq);
                            smg[wl*ASTRIDE + kb[u] + kw] = (unsigned char)(signed char)q;
                        }
                    }
                }
            }
        }
        __syncthreads();                   // SYNC2: A (and on iter 0, B) ready

        // ---- int8 MMA mainloop ----
        int acc[2][4][4];
#pragma unroll
        for (int i = 0; i < 2; i++)
#pragma unroll
            for (int j = 0; j < 4; j++)
#pragma unroll
                for (int r = 0; r < 4; r++) acc[i][j][r] = 0;

#pragma unroll 3
        for (int kk = 0; kk < 18; kk++) {
            int ko = kk*32;
            int a[2][4];
#pragma unroll
            for (int i = 0; i < 2; i++) {
                const unsigned char* p = aB + i*16*ASTRIDE + ko;
                a[i][0] = *(const int*)(p);
                a[i][1] = *(const int*)(p + 8*ASTRIDE);
                a[i][2] = *(const int*)(p + 16);
                a[i][3] = *(const int*)(p + 8*ASTRIDE + 16);
            }
            int bb[4][2];
#pragma unroll
            for (int j = 0; j < 4; j++) {
                const unsigned char* p = bB + j*8*ASTRIDE + ko;
                bb[j][0] = *(const int*)(p);
                bb[j][1] = *(const int*)(p + 16);
            }
#pragma unroll
            for (int i = 0; i < 2; i++)
#pragma unroll
                for (int j = 0; j < 4; j++)
                    mma_i8(acc[i][j], a[i], bb[j]);
        }
        __syncthreads();                   // SYNC3: done reading A before staging C

        // ---- single-pass epilogue: stage all 128n x 64m, then coalesced STG ----
#pragma unroll
        for (int i = 0; i < 2; i++)
#pragma unroll
            for (int j = 0; j < 4; j++)
#pragma unroll
                for (int dm = 0; dm < 2; dm++)
#pragma unroll
                    for (int dn = 0; dn < 2; dn++) {
                        int nloc = wn*32 + j*8 + tg*2 + dn;
                        int mloc = wm*32 + i*16 + g + dm*8;
                        sC[nloc*68 + mloc] = (float)acc[i][j][dm*2 + dn] * sxsw;
                    }
        __syncthreads();                   // SYNC4: C staged

#pragma unroll
        for (int r = 0; r < 32; r++) {
            int pos = r*256 + tid;
            int nl = pos >> 6, mm = pos & 63;    // consecutive tid -> consecutive l
            out[(size_t)(b*OUT_CH + nl)*IMG + l0 + mm] = sC[nl*68 + mm];
        }
        __syncthreads();                   // SYNC5: STG reads done before next zero
    }
}

// ---------------- launcher ----------------
extern "C" void kernel_launch(void* const* d_in, const int* in_sizes, int n_in,
                              void* d_out, int out_size) {
    const float* in = (const float*)d_in[0];   // (16,64,128,128) f32
    const float* w  = (const float*)d_in[1];   // (128,64,3,3) f32
    float* out = (float*)d_out;                // (16,128,128,128) f32

    k_zero  <<<1, KS>>>();
    k_act9  <<<NB*IN_CH, 256>>>(in);
    k_scales<<<1, KS>>>(w);
    k_quantw<<<OUT_CH, KS>>>(w);

    cudaFuncSetAttribute(k_gemm, cudaFuncAttributeMaxDynamicSharedMemorySize,
                         SMEM_GEMM_TOTAL);
    k_gemm  <<<GRID_P, 256, SMEM_GEMM_TOTAL>>>(in, out);
}

// round 16
// speedup vs baseline: 1.0907x; 1.0907x over previous
#include <cuda_runtime.h>
#include <cstdint>

#define IN_CH   64
#define OUT_CH  128
#define HW      128
#define IMG     (HW*HW)         // 16384
#define NB      16
#define KS      576             // IN_CH * 9
#define KW4     (KS/4)          // 144 words per row
#define M_TOTAL (NB*IMG)        // 262144
#define NTILES  (M_TOTAL/64)    // 4096

// ---------------- device scratch (static, no allocation) ----------------
__device__ unsigned int g_act9[KS];
__device__ float        g_scale[KS];
__device__ float        g_recip[KS];
__device__ float        g_params[4];                  // [0]=s_x, [1]=s_x*s_w, [2]=s_w
__device__ unsigned int g_qw[OUT_CH*KW4];             // int8 weights [o][k] packed

// ---------------- k0: zero the atomicMax target ----------------
__global__ void k_zero() {
    int t = threadIdx.x;
    if (t < KS) g_act9[t] = 0u;
}

// ---------------- k1: per-(c,kh,kw) activation amax over valid window ----------------
__global__ void k_act9(const float* __restrict__ in) {
    const float* p = in + (size_t)blockIdx.x * IMG;   // blockIdx = b*64 + c
    float loc[9];
#pragma unroll
    for (int i = 0; i < 9; i++) loc[i] = 0.f;

    for (int idx = threadIdx.x; idx < IMG; idx += blockDim.x) {
        int r = idx >> 7, c = idx & 127;
        float a = fabsf(p[idx]);
        bool rok[3] = { r <= 126, true, r >= 1 };
        bool cok[3] = { c <= 126, true, c >= 1 };
#pragma unroll
        for (int kh = 0; kh < 3; kh++)
#pragma unroll
            for (int kw = 0; kw < 3; kw++) {
                float v = (rok[kh] && cok[kw]) ? a : 0.f;
                loc[kh*3+kw] = fmaxf(loc[kh*3+kw], v);
            }
    }
#pragma unroll
    for (int i = 0; i < 9; i++)
        for (int o = 16; o > 0; o >>= 1)
            loc[i] = fmaxf(loc[i], __shfl_xor_sync(0xffffffffu, loc[i], o));

    __shared__ float sred[8][9];
    int wid = threadIdx.x >> 5, lane = threadIdx.x & 31;
    if (lane == 0)
        for (int i = 0; i < 9; i++) sred[wid][i] = loc[i];
    __syncthreads();
    if (threadIdx.x < 9) {
        float m = sred[0][threadIdx.x];
        for (int w = 1; w < 8; w++) m = fmaxf(m, sred[w][threadIdx.x]);
        int c = blockIdx.x & 63;
        atomicMax(&g_act9[c*9 + threadIdx.x], __float_as_uint(m));
    }
}

// ---------------- k2: scales + amaxes (weight quant in k_quantw) ----------------
__global__ void k_scales(const float* __restrict__ w) {
    __shared__ float red[KS];
    int t = threadIdx.x;

    float wm = 0.f;
    for (int o = 0; o < OUT_CH; o++) wm = fmaxf(wm, fabsf(w[o*KS + t]));

    float a = __uint_as_float(g_act9[t]);
    float s = __fdiv_rn(sqrtf(a), sqrtf(wm));
    if (s == 0.f) s = 1.f;
    g_scale[t] = s;

    red[t] = __fdiv_rn(a, s);
    __syncthreads();
    for (int st = 512; st > 0; st >>= 1) {
        if (t < st && t + st < KS) red[t] = fmaxf(red[t], red[t+st]);
        __syncthreads();
    }
    float xa = red[0];
    __syncthreads();

    float wq = 0.f;
    for (int o = 0; o < OUT_CH; o++) wq = fmaxf(wq, fabsf(w[o*KS + t] * s));
    red[t] = wq;
    __syncthreads();
    for (int st = 512; st > 0; st >>= 1) {
        if (t < st && t + st < KS) red[t] = fmaxf(red[t], red[t+st]);
        __syncthreads();
    }
    float wa = red[0];

    float sx = (xa > 0.f) ? __fdiv_rn(xa, 127.f) : 1.f;
    float sw = (wa > 0.f) ? __fdiv_rn(wa, 127.f) : 1.f;

    g_recip[t] = (float)(1.0 / ((double)s * (double)sx));
    if (t == 0) { g_params[0] = sx; g_params[1] = sx * sw; g_params[2] = sw; }
}

// ---------------- k2b: weight quantization, one block per output channel ----------------
__global__ void k_quantw(const float* __restrict__ w) {
    int o = blockIdx.x, t = threadIdx.x;               // 576 threads
    float sw = g_params[2];
    float v = w[o*KS + t] * g_scale[t];
    float q = rintf(__fdiv_rn(v, sw));                 // exact reference chain
    q = fminf(fmaxf(q, -127.f), 127.f);
    ((unsigned char*)g_qw)[o*KS + t] = (unsigned char)(signed char)(int)q;
}

// ---------------- k3: FUSED quantize + int8 GEMM (mma.sync m16n8k32, 2 CTAs/SM) ----------------
// BM=64, BN=128, K=576 resident, grid=4096 (one tile per CTA, HW-balanced).
// A-build uses the magic-number trick: FFMA(x, R_k, 2^23*1.5) puts
// round-half-even(x*R_k) two's-complement in the low byte -> STS.U8.
// Clamp is provably dead (|x*R_k| <= 127 + 2ulp by construction of R_k).
#define BM 64
#define ASTRIDE 592
#define SMEM_B_OFF (BM*ASTRIDE)                       // 37888
#define SMEM_GEMM_TOTAL (SMEM_B_OFF + 128*ASTRIDE)    // 113664
#define MAGIC 12582912.f                              // 1.5 * 2^23

__device__ __forceinline__ void mma_i8(int* c, const int* a, const int* b) {
    asm volatile(
        "mma.sync.aligned.m16n8k32.row.col.s32.s8.s8.s32 "
        "{%0,%1,%2,%3}, {%4,%5,%6,%7}, {%8,%9}, {%0,%1,%2,%3};"
        : "+r"(c[0]), "+r"(c[1]), "+r"(c[2]), "+r"(c[3])
        : "r"(a[0]), "r"(a[1]), "r"(a[2]), "r"(a[3]), "r"(b[0]), "r"(b[1]));
}

extern __shared__ unsigned char smg[];

__global__ void __launch_bounds__(256, 2) k_gemm(const float* __restrict__ in,
                                                 float* __restrict__ out) {
    int tid = threadIdx.x;
    int wid = tid >> 5, lane = tid & 31;
    int wm = wid >> 2, wn = wid & 3;       // warp tile: rows wm*32.., cols wn*32..
    int g  = lane >> 2, tg = lane & 3;     // groupID / threadInGroup
    int m0 = blockIdx.x * BM;
    int b  = m0 >> 14;                     // batch
    int h  = (m0 >> 7) & 127;              // image row
    int w0 = m0 & 127;                     // 0 or 64
    int l0 = m0 & 16383;

    // ---- stage B (weights, 128 rows x 576B): LDG.128 -> STS.128, L2-hot ----
    const uint4* gB = (const uint4*)g_qw;
    for (int idx = tid; idx < 128*36; idx += 256) {
        int row = idx / 36, j = idx - row*36;
        *(uint4*)(smg + SMEM_B_OFF + row*ASTRIDE + j*16) = gB[(size_t)row*36 + j];
    }

    // ---- zero-init A region (covers all padding cases) ----
    for (int idx = tid; idx < BM*37; idx += 256)
        *(uint4*)(smg + idx*16) = make_uint4(0,0,0,0);
    __syncthreads();                       // SYNC1

    // ---- build A: float4 chunks -> magic-FFMA quantize -> STS.U8 scatter ----
    // planes (c 0..63, r 0..2), 18 aligned float4 chunks over cols [w0-4, w0+68)
    for (int idx = tid; idx < 192*18; idx += 256) {
        int plane = idx / 18;
        int i     = idx - plane*18;
        int c     = plane / 3;
        int r     = plane - 3*c;
        int ih    = h + r - 1;
        int col0  = w0 - 4 + i*4;
        if ((unsigned)ih >= (unsigned)HW) continue;
        if ((unsigned)col0 >= (unsigned)HW) continue;

        float4 x = *(const float4*)(in + ((size_t)(b*IN_CH + c)*HW + ih)*HW + col0);
        int kb = plane*3;                  // c*9 + r*3
        float Rk[3] = { g_recip[kb], g_recip[kb+1], g_recip[kb+2] };
        float xv[4] = { x.x, x.y, x.z, x.w };
        int wb = col0 - w0 + 1;            // wl for e=0, kw=0
        unsigned char* bp = smg + wb*ASTRIDE + kb;

        if (wb >= 2 && wb <= 60) {
            // interior: all 12 slots valid, no predicates
#pragma unroll
            for (int e = 0; e < 4; e++)
#pragma unroll
                for (int kw = 0; kw < 3; kw++)
                    bp[(e - kw)*ASTRIDE + kw] =
                        (unsigned char)__float_as_uint(fmaf(xv[e], Rk[kw], MAGIC));
        } else {
#pragma unroll
            for (int e = 0; e < 4; e++)
#pragma unroll
                for (int kw = 0; kw < 3; kw++) {
                    int wl = wb + e - kw;
                    if ((unsigned)wl < (unsigned)BM)
                        smg[wl*ASTRIDE + kb + kw] =
                            (unsigned char)__float_as_uint(fmaf(xv[e], Rk[kw], MAGIC));
                }
        }
    }
    __syncthreads();                       // SYNC2: A and B ready

    // ---- int8 MMA mainloop ----
    int acc[2][4][4];
#pragma unroll
    for (int i = 0; i < 2; i++)
#pragma unroll
        for (int j = 0; j < 4; j++)
#pragma unroll
            for (int r = 0; r < 4; r++) acc[i][j][r] = 0;

    const unsigned char* aB = smg + (wm*32 + g)*ASTRIDE + tg*4;
    const unsigned char* bB = smg + SMEM_B_OFF + (wn*32 + g)*ASTRIDE + tg*4;

#pragma unroll 3
    for (int kk = 0; kk < 18; kk++) {
        int ko = kk*32;
        int a[2][4];
#pragma unroll
        for (int i = 0; i < 2; i++) {
            const unsigned char* p = aB + i*16*ASTRIDE + ko;
            a[i][0] = *(const int*)(p);
            a[i][1] = *(const int*)(p + 8*ASTRIDE);
            a[i][2] = *(const int*)(p + 16);
            a[i][3] = *(const int*)(p + 8*ASTRIDE + 16);
        }
        int bb[4][2];
#pragma unroll
        for (int j = 0; j < 4; j++) {
            const unsigned char* p = bB + j*8*ASTRIDE + ko;
            bb[j][0] = *(const int*)(p);
            bb[j][1] = *(const int*)(p + 16);
        }
#pragma unroll
        for (int i = 0; i < 2; i++)
#pragma unroll
            for (int j = 0; j < 4; j++)
                mma_i8(acc[i][j], a[i], bb[j]);
    }
    __syncthreads();                       // SYNC3: done reading A

    // ---- single-pass epilogue: stage 128n x 64m f32 in A region ----
    float sxsw = g_params[1];
    float* sC = (float*)smg;               // [128][68] floats = 34,816 B
#pragma unroll
    for (int i = 0; i < 2; i++)
#pragma unroll
        for (int j = 0; j < 4; j++)
#pragma unroll
            for (int dm = 0; dm < 2; dm++)
#pragma unroll
                for (int dn = 0; dn < 2; dn++) {
                    int nloc = wn*32 + j*8 + tg*2 + dn;
                    int mloc = wm*32 + i*16 + g + dm*8;
                    sC[nloc*68 + mloc] = (float)acc[i][j][dm*2 + dn] * sxsw;
                }
    __syncthreads();                       // SYNC4: C staged

    // vectorized readback: 2048 float4s, coalesced STG.128
#pragma unroll
    for (int r = 0; r < 8; r++) {
        int pos = r*256 + tid;
        int nl = pos >> 4, mq = pos & 15;
        float4 v = *(const float4*)&sC[nl*68 + mq*4];
        *(float4*)&out[(size_t)(b*OUT_CH + nl)*IMG + l0 + mq*4] = v;
    }
}

// ---------------- launcher ----------------
extern "C" void kernel_launch(void* const* d_in, const int* in_sizes, int n_in,
                              void* d_out, int out_size) {
    const float* in = (const float*)d_in[0];   // (16,64,128,128) f32
    const float* w  = (const float*)d_in[1];   // (128,64,3,3) f32
    float* out = (float*)d_out;                // (16,128,128,128) f32

    k_zero  <<<1, KS>>>();
    k_act9  <<<NB*IN_CH, 256>>>(in);
    k_scales<<<1, KS>>>(w);
    k_quantw<<<OUT_CH, KS>>>(w);

    cudaFuncSetAttribute(k_gemm, cudaFuncAttributeMaxDynamicSharedMemorySize,
                         SMEM_GEMM_TOTAL);
    k_gemm  <<<NTILES, 256, SMEM_GEMM_TOTAL>>>(in, out);
}